// round 12
// baseline (speedup 1.0000x reference)
#include <cuda_runtime.h>
#include <cuda_bf16.h>
#include <cstdint>

// GCN on complete graph + self-loops == per-batch mean pooling -> per-batch
// 4-layer MLP on the mean node feature.
// Tensor-core implementation via warp-level mma.sync.m16n8k16 (bf16, f32
// accum) with hi/lo bf16 split (3 MMAs per GEMM step, rel err ~2^-16).
// Kernel 1 (prep): converts W1/W2/Wm1 to transposed bf16 hi/lo arrays
// Wt[n][k] in __device__ globals (B fragments become single u32 LDGs).
// Kernel 2 (mlp): grid=128 CTAs x 8 rows (padded to M=16), NT=256.

#define NT 256
#define MR 8
#define KPAD 136   // activation k-stride (bank-conflict-free fragment LDS)

__device__ unsigned short g_w1hi[128 * 16],  g_w1lo[128 * 16];
__device__ unsigned short g_w2hi[128 * 128], g_w2lo[128 * 128];
__device__ unsigned short g_m1hi[128 * 128], g_m1lo[128 * 128];

__device__ __forceinline__ void split2f(float x, unsigned short& h, unsigned short& l) {
    __nv_bfloat16 hb = __float2bfloat16_rn(x);
    float r = x - __bfloat162float(hb);
    __nv_bfloat16 lb = __float2bfloat16_rn(r);
    h = __bfloat16_as_ushort(hb);
    l = __bfloat16_as_ushort(lb);
}

// grid = 128 (k), block = 128 (n): coalesced weight reads, scattered u16 writes
__global__ void prep_kernel(const float* __restrict__ W1,
                            const float* __restrict__ W2,
                            const float* __restrict__ Wm1) {
    const int k = blockIdx.x, n = threadIdx.x;
    unsigned short h, l;
    split2f(W2[k * 128 + n], h, l);
    g_w2hi[n * 128 + k] = h;  g_w2lo[n * 128 + k] = l;
    split2f(Wm1[k * 128 + n], h, l);
    g_m1hi[n * 128 + k] = h;  g_m1lo[n * 128 + k] = l;
    if (k < 16) {
        const float v = (k < 14) ? W1[k * 128 + n] : 0.f;
        split2f(v, h, l);
        g_w1hi[n * 16 + k] = h;  g_w1lo[n * 16 + k] = l;
    }
}

// pack (x0 -> low bf16, x1 -> high bf16), plus residual pair
__device__ __forceinline__ uint32_t packbf(float lo, float hi) {
    uint32_t r;
    asm("cvt.rn.bf16x2.f32 %0, %1, %2;" : "=r"(r) : "f"(hi), "f"(lo));
    return r;
}
__device__ __forceinline__ void split2u(float x0, float x1, uint32_t& hp, uint32_t& lp) {
    hp = packbf(x0, x1);
    const float h0 = __uint_as_float(hp << 16);
    const float h1 = __uint_as_float(hp & 0xFFFF0000u);
    lp = packbf(x0 - h0, x1 - h1);
}

__device__ __forceinline__ void mma16816(float c[4],
                                         uint32_t a0, uint32_t a1, uint32_t a2, uint32_t a3,
                                         uint32_t b0, uint32_t b1) {
    asm volatile(
        "mma.sync.aligned.m16n8k16.row.col.f32.bf16.bf16.f32 "
        "{%0,%1,%2,%3}, {%4,%5,%6,%7}, {%8,%9}, {%0,%1,%2,%3};"
        : "+f"(c[0]), "+f"(c[1]), "+f"(c[2]), "+f"(c[3])
        : "r"(a0), "r"(a1), "r"(a2), "r"(a3), "r"(b0), "r"(b1));
}

// One 128-k dense layer on tensor cores. In: smem act hi/lo [16][KPAD] bf16.
// Weights: global transposed bf16 hi/lo [128n][128k]. Out: either bf16 hi/lo
// act buffers (pair-packed u32 stores) or f32 sM[16][132].
template<bool F32OUT>
__device__ __forceinline__ void layer128(
    const unsigned short* __restrict__ sInHi, const unsigned short* __restrict__ sInLo,
    const unsigned short* __restrict__ gWhi,  const unsigned short* __restrict__ gWlo,
    const float* __restrict__ bias,
    unsigned short* __restrict__ sOutHi, unsigned short* __restrict__ sOutLo,
    float* __restrict__ sMout, int wid, int lane)
{
    const int g = lane >> 2, t = lane & 3;
    const int n0 = 2 * wid * 8 + g;      // B row for n-tile 0
    const int n1 = n0 + 8;               // n-tile 1
    float c0[4] = {0.f, 0.f, 0.f, 0.f};
    float c1[4] = {0.f, 0.f, 0.f, 0.f};

    #pragma unroll
    for (int s = 0; s < 8; s++) {
        const int ko = 16 * s + 2 * t;
        const uint32_t ah0 = *(const uint32_t*)(sInHi + g * KPAD + ko);
        const uint32_t ah1 = *(const uint32_t*)(sInHi + (g + 8) * KPAD + ko);
        const uint32_t ah2 = *(const uint32_t*)(sInHi + g * KPAD + ko + 8);
        const uint32_t ah3 = *(const uint32_t*)(sInHi + (g + 8) * KPAD + ko + 8);
        const uint32_t al0 = *(const uint32_t*)(sInLo + g * KPAD + ko);
        const uint32_t al1 = *(const uint32_t*)(sInLo + (g + 8) * KPAD + ko);
        const uint32_t al2 = *(const uint32_t*)(sInLo + g * KPAD + ko + 8);
        const uint32_t al3 = *(const uint32_t*)(sInLo + (g + 8) * KPAD + ko + 8);

        const uint32_t bh00 = *(const uint32_t*)(gWhi + n0 * 128 + ko);
        const uint32_t bh01 = *(const uint32_t*)(gWhi + n0 * 128 + ko + 8);
        const uint32_t bl00 = *(const uint32_t*)(gWlo + n0 * 128 + ko);
        const uint32_t bl01 = *(const uint32_t*)(gWlo + n0 * 128 + ko + 8);
        const uint32_t bh10 = *(const uint32_t*)(gWhi + n1 * 128 + ko);
        const uint32_t bh11 = *(const uint32_t*)(gWhi + n1 * 128 + ko + 8);
        const uint32_t bl10 = *(const uint32_t*)(gWlo + n1 * 128 + ko);
        const uint32_t bl11 = *(const uint32_t*)(gWlo + n1 * 128 + ko + 8);

        mma16816(c0, ah0, ah1, ah2, ah3, bh00, bh01);   // hi*hi
        mma16816(c0, ah0, ah1, ah2, ah3, bl00, bl01);   // hi*lo
        mma16816(c0, al0, al1, al2, al3, bh00, bh01);   // lo*hi
        mma16816(c1, ah0, ah1, ah2, ah3, bh10, bh11);
        mma16816(c1, ah0, ah1, ah2, ah3, bl10, bl11);
        mma16816(c1, al0, al1, al2, al3, bh10, bh11);
    }

    // epilogue: D layout c0/c1 = D[g][2t], D[g][2t+1], D[g+8][2t], D[g+8][2t+1]
    #pragma unroll
    for (int nt = 0; nt < 2; nt++) {
        const float* c = nt ? c1 : c0;
        const int col = 2 * wid * 8 + nt * 8 + 2 * t;
        const float bx = bias[col], by = bias[col + 1];
        const float x0 = fmaxf(c[0] + bx, 0.f);
        const float x1 = fmaxf(c[1] + by, 0.f);
        const float x2 = fmaxf(c[2] + bx, 0.f);
        const float x3 = fmaxf(c[3] + by, 0.f);
        if (F32OUT) {
            *(float2*)(sMout + g * 132 + col)       = make_float2(x0, x1);
            *(float2*)(sMout + (g + 8) * 132 + col) = make_float2(x2, x3);
        } else {
            uint32_t hp, lp;
            split2u(x0, x1, hp, lp);
            *(uint32_t*)(sOutHi + g * KPAD + col) = hp;
            *(uint32_t*)(sOutLo + g * KPAD + col) = lp;
            split2u(x2, x3, hp, lp);
            *(uint32_t*)(sOutHi + (g + 8) * KPAD + col) = hp;
            *(uint32_t*)(sOutLo + (g + 8) * KPAD + col) = lp;
        }
    }
}

__global__ __launch_bounds__(NT) void mlp_kernel(
    const float* __restrict__ obs,
    const float* __restrict__ b1, const float* __restrict__ b2,
    const float* __restrict__ bm1,
    const float* __restrict__ Wm2, const float* __restrict__ bm2,
    float* __restrict__ out, int std_off)
{
    __shared__ __align__(16) unsigned short sA1h[16 * KPAD], sA1l[16 * KPAD];
    __shared__ __align__(16) unsigned short sA2h[16 * KPAD], sA2l[16 * KPAD];
    __shared__ float sM[16 * 132];
    __shared__ float sB1[128], sB2[128], sBm1[128], sWm2v[512], sBm2[4];
    __shared__ float sP[256], sO[32];

    const int tid = threadIdx.x, wid = tid >> 5, lane = tid & 31;
    const int base = blockIdx.x * MR;

    // zero A1 (covers padded rows 8-15 and pad cols)
    #pragma unroll
    for (int i = tid; i < 16 * KPAD / 2; i += NT) {
        ((uint32_t*)sA1h)[i] = 0u;
        ((uint32_t*)sA1l)[i] = 0u;
    }
    if (tid < 128) { sB1[tid] = b1[tid]; sB2[tid] = b2[tid]; sBm1[tid] = bm1[tid]; }
    sWm2v[tid] = Wm2[tid];
    sWm2v[tid + 256] = Wm2[tid + 256];
    if (tid < 4) sBm2[tid] = bm2[tid];
    __syncthreads();

    // fbar -> A1 (bf16 hi/lo), rows 0-7, feature dims 0-13 (obs dims 2-15)
    if (tid < 64) {
        const int r = tid >> 3, p = tid & 7;
        if (p < 7) {
            const float* q = obs + (size_t)(base + r) * 512 + 2 + 2 * p;
            float s0 = 0.f, s1 = 0.f;
            #pragma unroll
            for (int n = 0; n < 32; n++) {
                const float2 v = *(const float2*)(q + n * 16);
                s0 += v.x; s1 += v.y;
            }
            uint32_t hp, lp;
            split2u(s0 * 0.03125f, s1 * 0.03125f, hp, lp);
            *(uint32_t*)(sA1h + r * KPAD + 2 * p) = hp;
            *(uint32_t*)(sA1l + r * KPAD + 2 * p) = lp;
        }
    }
    __syncthreads();

    // ---- L1: h1 = relu(fbar @ W1 + b1), K=16 (one MMA step) ----
    {
        const int g = lane >> 2, t = lane & 3;
        const int ko = 2 * t;
        float c0[4] = {0.f, 0.f, 0.f, 0.f};
        float c1[4] = {0.f, 0.f, 0.f, 0.f};
        const uint32_t ah0 = *(const uint32_t*)(sA1h + g * KPAD + ko);
        const uint32_t ah1 = *(const uint32_t*)(sA1h + (g + 8) * KPAD + ko);
        const uint32_t ah2 = *(const uint32_t*)(sA1h + g * KPAD + ko + 8);
        const uint32_t ah3 = *(const uint32_t*)(sA1h + (g + 8) * KPAD + ko + 8);
        const uint32_t al0 = *(const uint32_t*)(sA1l + g * KPAD + ko);
        const uint32_t al1 = *(const uint32_t*)(sA1l + (g + 8) * KPAD + ko);
        const uint32_t al2 = *(const uint32_t*)(sA1l + g * KPAD + ko + 8);
        const uint32_t al3 = *(const uint32_t*)(sA1l + (g + 8) * KPAD + ko + 8);
        const int n0 = 2 * wid * 8 + g, n1 = n0 + 8;
        const uint32_t bh00 = *(const uint32_t*)(g_w1hi + n0 * 16 + ko);
        const uint32_t bh01 = *(const uint32_t*)(g_w1hi + n0 * 16 + ko + 8);
        const uint32_t bl00 = *(const uint32_t*)(g_w1lo + n0 * 16 + ko);
        const uint32_t bl01 = *(const uint32_t*)(g_w1lo + n0 * 16 + ko + 8);
        const uint32_t bh10 = *(const uint32_t*)(g_w1hi + n1 * 16 + ko);
        const uint32_t bh11 = *(const uint32_t*)(g_w1hi + n1 * 16 + ko + 8);
        const uint32_t bl10 = *(const uint32_t*)(g_w1lo + n1 * 16 + ko);
        const uint32_t bl11 = *(const uint32_t*)(g_w1lo + n1 * 16 + ko + 8);
        mma16816(c0, ah0, ah1, ah2, ah3, bh00, bh01);
        mma16816(c0, ah0, ah1, ah2, ah3, bl00, bl01);
        mma16816(c0, al0, al1, al2, al3, bh00, bh01);
        mma16816(c1, ah0, ah1, ah2, ah3, bh10, bh11);
        mma16816(c1, ah0, ah1, ah2, ah3, bl10, bl11);
        mma16816(c1, al0, al1, al2, al3, bh10, bh11);
        #pragma unroll
        for (int nt = 0; nt < 2; nt++) {
            const float* c = nt ? c1 : c0;
            const int col = 2 * wid * 8 + nt * 8 + 2 * t;
            const float bx = sB1[col], by = sB1[col + 1];
            uint32_t hp, lp;
            split2u(fmaxf(c[0] + bx, 0.f), fmaxf(c[1] + by, 0.f), hp, lp);
            *(uint32_t*)(sA2h + g * KPAD + col) = hp;
            *(uint32_t*)(sA2l + g * KPAD + col) = lp;
            split2u(fmaxf(c[2] + bx, 0.f), fmaxf(c[3] + by, 0.f), hp, lp);
            *(uint32_t*)(sA2h + (g + 8) * KPAD + col) = hp;
            *(uint32_t*)(sA2l + (g + 8) * KPAD + col) = lp;
        }
    }
    __syncthreads();

    // ---- L2: h2 = relu(h1 @ W2 + b2) : A2 -> A1 ----
    layer128<false>(sA2h, sA2l, g_w2hi, g_w2lo, sB2, sA1h, sA1l, nullptr, wid, lane);
    __syncthreads();

    // ---- L3: m = relu(h2 @ Wm1 + bm1) : A1 -> sM (f32) ----
    layer128<true>(sA1h, sA1l, g_m1hi, g_m1lo, sBm1, nullptr, nullptr, sM, wid, lane);
    __syncthreads();

    // ---- tail: o = m @ Wm2 + bm2 (8 real rows x 4 outs x 8 k-slices) ----
    {
        const int r = tid >> 5, cc = (tid >> 3) & 3, s = tid & 7;
        float p = 0.f;
        #pragma unroll
        for (int i = 0; i < 16; i++) {
            const int k = s * 16 + i;
            p = fmaf(sM[r * 132 + k], sWm2v[k * 4 + cc], p);
        }
        sP[tid] = p;
    }
    __syncthreads();
    if (tid < 32) {
        const int r = tid >> 2, cc = tid & 3;
        float o = sBm2[cc];
        #pragma unroll
        for (int s = 0; s < 8; s++) o += sP[r * 32 + cc * 8 + s];
        if (cc >= 2) o = __expf(-5.0f + 3.5f * (tanhf(o) + 1.0f));
        sO[r * 4 + cc] = o;   // [mu0, mu1, std0, std1]
    }
    __syncthreads();

    // ---- write: mu/std replicated x32, one float4 per thread ----
    {
        const int plane = tid >> 7, r = (tid >> 4) & 7, q2 = tid & 15;
        const float v0 = sO[r * 4 + 2 * plane];
        const float v1 = sO[r * 4 + 2 * plane + 1];
        float* dst = out + (plane ? (size_t)std_off : 0) + (size_t)(base + r) * 64;
        ((float4*)dst)[q2] = make_float4(v0, v1, v0, v1);
    }
}

extern "C" void kernel_launch(void* const* d_in, const int* in_sizes, int n_in,
                              void* d_out, int out_size) {
    const float* obs = (const float*)d_in[0];
    const float* W1  = (const float*)d_in[1];
    const float* b1  = (const float*)d_in[2];
    const float* W2  = (const float*)d_in[3];
    const float* b2  = (const float*)d_in[4];
    const float* Wm1 = (const float*)d_in[5];
    const float* bm1 = (const float*)d_in[6];
    const float* Wm2 = (const float*)d_in[7];
    const float* bm2 = (const float*)d_in[8];
    float* out = (float*)d_out;

    const int bs = in_sizes[0] / 512;     // 1024
    const int std_off = bs * 64;
    const int grid = bs / MR;             // 128

    prep_kernel<<<128, 128>>>(W1, W2, Wm1);
    mlp_kernel<<<grid, NT>>>(obs, b1, b2, bm1, Wm2, bm2, out, std_off);
}

// round 13
// speedup vs baseline: 1.3233x; 1.3233x over previous
#include <cuda_runtime.h>
#include <cuda_bf16.h>
#include <cstdint>

// GCN on complete graph + self-loops == per-batch mean pooling -> per-batch
// 4-layer MLP on the mean node feature.
// Tensor cores via warp-level mma.sync.m16n8k16 (bf16, f32 accum) with hi/lo
// split (3 MMAs per step). R13: B operands fed from SMEM (TMA-staged,
// k-stride 136 = bank-conflict-free), full M=16 tile (grid=64, NT=512).

#define NT 512
#define MR 16
#define KPAD 136   // u16 k-stride for activations AND weights (conflict-free)

// prep output: transposed, k-padded bf16 hi/lo weights
__device__ unsigned short g_w1hi[128 * 16],   g_w1lo[128 * 16];
__device__ unsigned short g_w2hi[128 * KPAD], g_w2lo[128 * KPAD];
__device__ unsigned short g_m1hi[128 * KPAD], g_m1lo[128 * KPAD];

// ---- dynamic smem byte offsets ----
#define OW2H 0
#define WBYTES (128 * KPAD * 2)        // 34816
#define OW2L (OW2H + WBYTES)
#define OM1H (OW2L + WBYTES)
#define OM1L (OM1H + WBYTES)
#define OA1H (OM1L + WBYTES)           // 139264
#define ABYTES (MR * KPAD * 2)         // 4352
#define OA1L (OA1H + ABYTES)
#define OA2H (OA1L + ABYTES)
#define OA2L (OA2H + ABYTES)
#define OSM  (OA2L + ABYTES)           // 156672, f32 [16][132]
#define OB1V (OSM + 16 * 132 * 4)      // 165120
#define OB2V (OB1V + 512)
#define OBM1 (OB2V + 512)
#define OWM2 (OBM1 + 512)              // 128x4 f32
#define OBM2 (OWM2 + 2048)             // 16B
#define OSP  (OBM2 + 16)               // 512 f32 tail partials
#define OSO  (OSP + 2048)              // 16x4 f32
#define OMB  (OSO + 256)               // mbarrier (8B-aligned)
#define SMEM_BYTES (OMB + 16)

__device__ __forceinline__ uint32_t s2u(const void* p) {
    return (uint32_t)__cvta_generic_to_shared(p);
}
#define MBARRIER_INIT(mb, c) \
    asm volatile("mbarrier.init.shared.b64 [%0], %1;" :: "r"(mb), "r"(c) : "memory")
__device__ __forceinline__ void mbar_expect(uint32_t a, uint32_t bytes) {
    asm volatile("mbarrier.arrive.expect_tx.shared.b64 _, [%0], %1;"
                 :: "r"(a), "r"(bytes) : "memory");
}
__device__ __forceinline__ void bulk_g2s(uint32_t dst, const void* src,
                                         uint32_t bytes, uint32_t mbar) {
    asm volatile("cp.async.bulk.shared::cluster.global.mbarrier::complete_tx::bytes "
                 "[%0], [%1], %2, [%3];"
                 :: "r"(dst), "l"(src), "r"(bytes), "r"(mbar) : "memory");
}
__device__ __forceinline__ void mbar_wait(uint32_t a, uint32_t parity) {
    asm volatile(
        "{\n\t.reg .pred P;\n"
        "WAIT_%=:\n\t"
        "mbarrier.try_wait.parity.shared.b64 P, [%0], %1, 0x989680;\n\t"
        "@P bra.uni DONE_%=;\n\t"
        "bra.uni WAIT_%=;\n"
        "DONE_%=:\n\t}"
        :: "r"(a), "r"(parity) : "memory");
}

__device__ __forceinline__ void split2f(float x, unsigned short& h, unsigned short& l) {
    __nv_bfloat16 hb = __float2bfloat16_rn(x);
    float r = x - __bfloat162float(hb);
    __nv_bfloat16 lb = __float2bfloat16_rn(r);
    h = __bfloat16_as_ushort(hb);
    l = __bfloat16_as_ushort(lb);
}

// grid = 128 (k), block = 128 (n)
__global__ void prep_kernel(const float* __restrict__ W1,
                            const float* __restrict__ W2,
                            const float* __restrict__ Wm1) {
    const int k = blockIdx.x, n = threadIdx.x;
    unsigned short h, l;
    split2f(W2[k * 128 + n], h, l);
    g_w2hi[n * KPAD + k] = h;  g_w2lo[n * KPAD + k] = l;
    split2f(Wm1[k * 128 + n], h, l);
    g_m1hi[n * KPAD + k] = h;  g_m1lo[n * KPAD + k] = l;
    if (k < 16) {
        const float v = (k < 14) ? W1[k * 128 + n] : 0.f;
        split2f(v, h, l);
        g_w1hi[n * 16 + k] = h;  g_w1lo[n * 16 + k] = l;
    }
}

__device__ __forceinline__ uint32_t packbf(float lo, float hi) {
    uint32_t r;
    asm("cvt.rn.bf16x2.f32 %0, %1, %2;" : "=r"(r) : "f"(hi), "f"(lo));
    return r;
}
__device__ __forceinline__ void split2u(float x0, float x1, uint32_t& hp, uint32_t& lp) {
    hp = packbf(x0, x1);
    const float h0 = __uint_as_float(hp << 16);
    const float h1 = __uint_as_float(hp & 0xFFFF0000u);
    lp = packbf(x0 - h0, x1 - h1);
}

__device__ __forceinline__ void mma16816(float c[4],
                                         uint32_t a0, uint32_t a1, uint32_t a2, uint32_t a3,
                                         uint32_t b0, uint32_t b1) {
    asm volatile(
        "mma.sync.aligned.m16n8k16.row.col.f32.bf16.bf16.f32 "
        "{%0,%1,%2,%3}, {%4,%5,%6,%7}, {%8,%9}, {%0,%1,%2,%3};"
        : "+f"(c[0]), "+f"(c[1]), "+f"(c[2]), "+f"(c[3])
        : "r"(a0), "r"(a1), "r"(a2), "r"(a3), "r"(b0), "r"(b1));
}

// One 128-k layer: act hi/lo in smem [16][KPAD], weights hi/lo in smem
// [128n][KPAD]. 16 warps x one 8-col n-tile. Output: bf16 hi/lo act buffers
// or f32 sM[16][132].
template<bool F32OUT>
__device__ __forceinline__ void layer128(
    const unsigned short* __restrict__ sInHi, const unsigned short* __restrict__ sInLo,
    const unsigned short* __restrict__ sWhi,  const unsigned short* __restrict__ sWlo,
    const float* __restrict__ bias,
    unsigned short* __restrict__ sOutHi, unsigned short* __restrict__ sOutLo,
    float* __restrict__ sMout, int wid, int lane)
{
    const int g = lane >> 2, t = lane & 3;
    const int n0 = wid * 8 + g;
    float c0[4] = {0.f, 0.f, 0.f, 0.f};

    #pragma unroll
    for (int s = 0; s < 8; s++) {
        const int ko = 16 * s + 2 * t;
        const uint32_t ah0 = *(const uint32_t*)(sInHi + g * KPAD + ko);
        const uint32_t ah1 = *(const uint32_t*)(sInHi + (g + 8) * KPAD + ko);
        const uint32_t ah2 = *(const uint32_t*)(sInHi + g * KPAD + ko + 8);
        const uint32_t ah3 = *(const uint32_t*)(sInHi + (g + 8) * KPAD + ko + 8);
        const uint32_t al0 = *(const uint32_t*)(sInLo + g * KPAD + ko);
        const uint32_t al1 = *(const uint32_t*)(sInLo + (g + 8) * KPAD + ko);
        const uint32_t al2 = *(const uint32_t*)(sInLo + g * KPAD + ko + 8);
        const uint32_t al3 = *(const uint32_t*)(sInLo + (g + 8) * KPAD + ko + 8);

        const uint32_t bh0 = *(const uint32_t*)(sWhi + n0 * KPAD + ko);
        const uint32_t bh1 = *(const uint32_t*)(sWhi + n0 * KPAD + ko + 8);
        const uint32_t bl0 = *(const uint32_t*)(sWlo + n0 * KPAD + ko);
        const uint32_t bl1 = *(const uint32_t*)(sWlo + n0 * KPAD + ko + 8);

        mma16816(c0, ah0, ah1, ah2, ah3, bh0, bh1);   // hi*hi
        mma16816(c0, ah0, ah1, ah2, ah3, bl0, bl1);   // hi*lo
        mma16816(c0, al0, al1, al2, al3, bh0, bh1);   // lo*hi
    }

    const int col = wid * 8 + 2 * t;
    const float bx = bias[col], by = bias[col + 1];
    const float x0 = fmaxf(c0[0] + bx, 0.f);
    const float x1 = fmaxf(c0[1] + by, 0.f);
    const float x2 = fmaxf(c0[2] + bx, 0.f);
    const float x3 = fmaxf(c0[3] + by, 0.f);
    if (F32OUT) {
        *(float2*)(sMout + g * 132 + col)       = make_float2(x0, x1);
        *(float2*)(sMout + (g + 8) * 132 + col) = make_float2(x2, x3);
    } else {
        uint32_t hp, lp;
        split2u(x0, x1, hp, lp);
        *(uint32_t*)(sOutHi + g * KPAD + col) = hp;
        *(uint32_t*)(sOutLo + g * KPAD + col) = lp;
        split2u(x2, x3, hp, lp);
        *(uint32_t*)(sOutHi + (g + 8) * KPAD + col) = hp;
        *(uint32_t*)(sOutLo + (g + 8) * KPAD + col) = lp;
    }
}

__global__ __launch_bounds__(NT, 1) void mlp_kernel(
    const float* __restrict__ obs,
    const float* __restrict__ b1, const float* __restrict__ b2,
    const float* __restrict__ bm1,
    const float* __restrict__ Wm2, const float* __restrict__ bm2,
    float* __restrict__ out, int std_off)
{
    extern __shared__ __align__(16) char smem[];
    unsigned short* sW2h = (unsigned short*)(smem + OW2H);
    unsigned short* sW2l = (unsigned short*)(smem + OW2L);
    unsigned short* sM1h = (unsigned short*)(smem + OM1H);
    unsigned short* sM1l = (unsigned short*)(smem + OM1L);
    unsigned short* sA1h = (unsigned short*)(smem + OA1H);
    unsigned short* sA1l = (unsigned short*)(smem + OA1L);
    unsigned short* sA2h = (unsigned short*)(smem + OA2H);
    unsigned short* sA2l = (unsigned short*)(smem + OA2L);
    float* sM    = (float*)(smem + OSM);
    float* sB1   = (float*)(smem + OB1V);
    float* sB2   = (float*)(smem + OB2V);
    float* sBm1  = (float*)(smem + OBM1);
    float* sWm2v = (float*)(smem + OWM2);
    float* sBm2  = (float*)(smem + OBM2);
    float* sP    = (float*)(smem + OSP);
    float* sO    = (float*)(smem + OSO);

    const int tid = threadIdx.x, wid = tid >> 5, lane = tid & 31;
    const int base = blockIdx.x * MR;
    const uint32_t mbar = s2u(smem + OMB);

    if (tid == 0) MBARRIER_INIT(mbar, 1);
    __syncthreads();
    if (tid == 0) {
        mbar_expect(mbar, 4 * WBYTES);
        bulk_g2s(s2u(smem + OW2H), g_w2hi, WBYTES, mbar);
        bulk_g2s(s2u(smem + OW2L), g_w2lo, WBYTES, mbar);
        bulk_g2s(s2u(smem + OM1H), g_m1hi, WBYTES, mbar);
        bulk_g2s(s2u(smem + OM1L), g_m1lo, WBYTES, mbar);
    }

    // zero A1 (pad cols for L1's K=16 tile: dims 14,15 must be 0)
    #pragma unroll
    for (int i = tid; i < MR * KPAD / 2; i += NT) {
        ((uint32_t*)sA1h)[i] = 0u;
        ((uint32_t*)sA1l)[i] = 0u;
    }
    if (tid < 128) { sB1[tid] = b1[tid]; sB2[tid] = b2[tid]; sBm1[tid] = bm1[tid]; }
    if (tid < 512) sWm2v[tid & 511] = Wm2[tid & 511];
    if (tid < 4) sBm2[tid] = bm2[tid];
    __syncthreads();

    // fbar -> A1 (bf16 hi/lo): 128 threads, r = tid>>3 (16 rows), p = tid&7
    if (tid < 128) {
        const int r = tid >> 3, p = tid & 7;
        if (p < 7) {
            const float* q = obs + (size_t)(base + r) * 512 + 2 + 2 * p;
            float s0 = 0.f, s1 = 0.f;
            #pragma unroll
            for (int n = 0; n < 32; n++) {
                const float2 v = *(const float2*)(q + n * 16);
                s0 += v.x; s1 += v.y;
            }
            uint32_t hp, lp;
            split2u(s0 * 0.03125f, s1 * 0.03125f, hp, lp);
            *(uint32_t*)(sA1h + r * KPAD + 2 * p) = hp;
            *(uint32_t*)(sA1l + r * KPAD + 2 * p) = lp;
        }
    }
    __syncthreads();

    // ---- L1: h1 = relu(fbar @ W1 + b1), K=16 (W1 frags via small LDG) ----
    {
        const int g = lane >> 2, t = lane & 3;
        const int ko = 2 * t;
        const int n0 = wid * 8 + g;
        float c0[4] = {0.f, 0.f, 0.f, 0.f};
        const uint32_t ah0 = *(const uint32_t*)(sA1h + g * KPAD + ko);
        const uint32_t ah1 = *(const uint32_t*)(sA1h + (g + 8) * KPAD + ko);
        const uint32_t ah2 = *(const uint32_t*)(sA1h + g * KPAD + ko + 8);
        const uint32_t ah3 = *(const uint32_t*)(sA1h + (g + 8) * KPAD + ko + 8);
        const uint32_t al0 = *(const uint32_t*)(sA1l + g * KPAD + ko);
        const uint32_t al1 = *(const uint32_t*)(sA1l + (g + 8) * KPAD + ko);
        const uint32_t al2 = *(const uint32_t*)(sA1l + g * KPAD + ko + 8);
        const uint32_t al3 = *(const uint32_t*)(sA1l + (g + 8) * KPAD + ko + 8);
        const uint32_t bh0 = *(const uint32_t*)(g_w1hi + n0 * 16 + ko);
        const uint32_t bh1 = *(const uint32_t*)(g_w1hi + n0 * 16 + ko + 8);
        const uint32_t bl0 = *(const uint32_t*)(g_w1lo + n0 * 16 + ko);
        const uint32_t bl1 = *(const uint32_t*)(g_w1lo + n0 * 16 + ko + 8);
        mma16816(c0, ah0, ah1, ah2, ah3, bh0, bh1);
        mma16816(c0, ah0, ah1, ah2, ah3, bl0, bl1);
        mma16816(c0, al0, al1, al2, al3, bh0, bh1);
        const int col = wid * 8 + 2 * t;
        const float bx = sB1[col], by = sB1[col + 1];
        uint32_t hp, lp;
        split2u(fmaxf(c0[0] + bx, 0.f), fmaxf(c0[1] + by, 0.f), hp, lp);
        *(uint32_t*)(sA2h + g * KPAD + col) = hp;
        *(uint32_t*)(sA2l + g * KPAD + col) = lp;
        split2u(fmaxf(c0[2] + bx, 0.f), fmaxf(c0[3] + by, 0.f), hp, lp);
        *(uint32_t*)(sA2h + (g + 8) * KPAD + col) = hp;
        *(uint32_t*)(sA2l + (g + 8) * KPAD + col) = lp;
    }

    // ---- weights staged? ----
    mbar_wait(mbar, 0);
    __syncthreads();

    // ---- L2: h2 = relu(h1 @ W2 + b2) : A2 -> A1 ----
    layer128<false>(sA2h, sA2l, sW2h, sW2l, sB2, sA1h, sA1l, nullptr, wid, lane);
    __syncthreads();

    // ---- L3: m = relu(h2 @ Wm1 + bm1) : A1 -> sM (f32) ----
    layer128<true>(sA1h, sA1l, sM1h, sM1l, sBm1, nullptr, nullptr, sM, wid, lane);
    __syncthreads();

    // ---- tail: o = m @ Wm2 + bm2 : 512 = 16r x 4c x 8s(16k) ----
    {
        const int r = tid >> 5, cc = (tid >> 3) & 3, s = tid & 7;
        float p = 0.f;
        #pragma unroll
        for (int i = 0; i < 16; i++) {
            const int k = s * 16 + i;
            p = fmaf(sM[r * 132 + k], sWm2v[k * 4 + cc], p);
        }
        sP[tid] = p;
    }
    __syncthreads();
    if (tid < 64) {
        const int r = tid >> 2, cc = tid & 3;
        float o = sBm2[cc];
        #pragma unroll
        for (int s = 0; s < 8; s++) o += sP[r * 32 + cc * 8 + s];
        if (cc >= 2) o = __expf(-5.0f + 3.5f * (tanhf(o) + 1.0f));
        sO[r * 4 + cc] = o;    // [mu0, mu1, std0, std1]
    }
    __syncthreads();

    // ---- write: 512 float4 stores, one per thread ----
    {
        const int plane = tid >> 8;           // 0 = mu, 1 = std
        const int r = (tid >> 4) & 15;
        const int q = tid & 15;
        const float v0 = sO[r * 4 + 2 * plane];
        const float v1 = sO[r * 4 + 2 * plane + 1];
        float* dst = out + (plane ? (size_t)std_off : 0) + (size_t)(base + r) * 64;
        ((float4*)dst)[q] = make_float4(v0, v1, v0, v1);
    }
}

extern "C" void kernel_launch(void* const* d_in, const int* in_sizes, int n_in,
                              void* d_out, int out_size) {
    const float* obs = (const float*)d_in[0];
    const float* W1  = (const float*)d_in[1];
    const float* b1  = (const float*)d_in[2];
    const float* W2  = (const float*)d_in[3];
    const float* b2  = (const float*)d_in[4];
    const float* Wm1 = (const float*)d_in[5];
    const float* bm1 = (const float*)d_in[6];
    const float* Wm2 = (const float*)d_in[7];
    const float* bm2 = (const float*)d_in[8];
    float* out = (float*)d_out;

    const int bs = in_sizes[0] / 512;     // 1024
    const int std_off = bs * 64;
    const int grid = bs / MR;             // 64

    prep_kernel<<<128, 128>>>(W1, W2, Wm1);
    cudaFuncSetAttribute(mlp_kernel,
                         cudaFuncAttributeMaxDynamicSharedMemorySize, SMEM_BYTES);
    mlp_kernel<<<grid, NT, SMEM_BYTES>>>(obs, b1, b2, bm1, Wm2, bm2, out, std_off);
}